// round 17
// baseline (speedup 1.0000x reference)
#include <cuda_runtime.h>
#include <cuda_bf16.h>
#include <cstdint>

#define Bsz 4
#define Seq 2048
#define Dm  1024
#define Hn  16
#define Hd  64
#define Mrows (Bsz*Seq)   // 8192

// Scratch (allocation-free rule: __device__ globals)
__device__ __nv_bfloat16 g_xhi[Mrows*Dm],  g_xlo[Mrows*Dm];
__device__ __nv_bfloat16 g_whi[4][Dm*Dm],  g_wlo[4][Dm*Dm];
__device__ __nv_bfloat16 g_ahi[Bsz*Seq*Dm], g_alo[Bsz*Seq*Dm];
__device__ __nv_bfloat16 g_qhi[Bsz*Hn*Seq*Hd], g_qlo[Bsz*Hn*Seq*Hd];  // pre-scaled 1/8
__device__ __nv_bfloat16 g_khi[Bsz*Hn*Seq*Hd], g_klo[Bsz*Hn*Seq*Hd];
__device__ __nv_bfloat16 g_vthi[Bsz*Hn*Hd*Seq], g_vtlo[Bsz*Hn*Hd*Seq]; // [B,H,HD,S]

// ===========================================================================
// Common helpers
// ===========================================================================
__device__ __forceinline__ uint32_t smem_u32(const void* p) {
    uint32_t a;
    asm("{ .reg .u64 t; cvta.to.shared.u64 t, %1; cvt.u32.u64 %0, t; }"
        : "=r"(a) : "l"(p));
    return a;
}

#define CP16(dst, src) \
    asm volatile("cp.async.cg.shared.global [%0], [%1], 16;" :: "r"(dst), "l"(src))
#define CP_COMMIT()  asm volatile("cp.async.commit_group;" ::: "memory")
#define CP_WAIT1()   asm volatile("cp.async.wait_group 1;" ::: "memory")
#define CP_WAIT2()   asm volatile("cp.async.wait_group 2;" ::: "memory")
#define CP_WAIT0()   asm volatile("cp.async.wait_group 0;" ::: "memory")

#define LDSM4(r, addr) \
    asm volatile("ldmatrix.sync.aligned.m8n8.x4.shared.b16 {%0,%1,%2,%3}, [%4];" \
        : "=r"((r)[0]), "=r"((r)[1]), "=r"((r)[2]), "=r"((r)[3]) : "r"(addr))

__device__ __forceinline__ void mma_bf16_16x8x16(float c[4], const uint32_t a[4],
                                                 uint32_t b0, uint32_t b1) {
    asm volatile(
        "mma.sync.aligned.m16n8k16.row.col.f32.bf16.bf16.f32 "
        "{%0,%1,%2,%3}, {%4,%5,%6,%7}, {%8,%9}, {%0,%1,%2,%3};"
        : "+f"(c[0]), "+f"(c[1]), "+f"(c[2]), "+f"(c[3])
        : "r"(a[0]), "r"(a[1]), "r"(a[2]), "r"(a[3]), "r"(b0), "r"(b1));
}

// Split pair of fp32 -> packed bf16x2 hi + lo
__device__ __forceinline__ void splitb(float x, float y, uint32_t& hi, uint32_t& lo) {
    __nv_bfloat162 h;
    h.x = __float2bfloat16_rn(x);
    h.y = __float2bfloat16_rn(y);
    __nv_bfloat162 l;
    l.x = __float2bfloat16_rn(x - __bfloat162float(h.x));
    l.y = __float2bfloat16_rn(y - __bfloat162float(h.y));
    hi = *(uint32_t*)&h;
    lo = *(uint32_t*)&l;
}

// ===========================================================================
// Split pre-pass: X and 4 W matrices -> bf16 hi/lo planes
// ===========================================================================
__global__ __launch_bounds__(256)
void split_xw(const float* __restrict__ X,
              const float* __restrict__ Wq, const float* __restrict__ Wk,
              const float* __restrict__ Wv, const float* __restrict__ Wo)
{
    const int z = blockIdx.y;
    const float* src;
    __nv_bfloat16 *dhi, *dlo;
    int n4;
    if (z == 0)      { src = X;  dhi = g_xhi;    dlo = g_xlo;    n4 = Mrows*Dm/4; }
    else if (z == 1) { src = Wq; dhi = g_whi[0]; dlo = g_wlo[0]; n4 = Dm*Dm/4; }
    else if (z == 2) { src = Wk; dhi = g_whi[1]; dlo = g_wlo[1]; n4 = Dm*Dm/4; }
    else if (z == 3) { src = Wv; dhi = g_whi[2]; dlo = g_wlo[2]; n4 = Dm*Dm/4; }
    else             { src = Wo; dhi = g_whi[3]; dlo = g_wlo[3]; n4 = Dm*Dm/4; }

    for (int i = blockIdx.x * blockDim.x + threadIdx.x; i < n4;
         i += gridDim.x * blockDim.x) {
        float4 v = ((const float4*)src)[i];
        uint32_t h0, l0, h1, l1;
        splitb(v.x, v.y, h0, l0);
        splitb(v.z, v.w, h1, l1);
        *(uint2*)&dhi[4*i] = make_uint2(h0, h1);
        *(uint2*)&dlo[4*i] = make_uint2(l0, l1);
    }
}

// ===========================================================================
// 3xBF16 GEMM, 4-stage cp.async pipeline (KTB=16), single sync per stage.
// C[128x128], K=1024. LDSM fragment loads. GROW=48 (16B-aligned rows,
// conflict-free: 8 rows x 48B -> offsets mod 128 all distinct 16B banks).
// ===========================================================================
#define KTB   16
#define GROW  48                      // bytes per row: 32B data + 16B pad
#define PLANE_B (128*GROW)            // 6144 bytes per plane
#define STG_B   (4*PLANE_B)           // 24576 bytes per stage
#define NPIPE 4
#define GEMM_SMEM_BYTES (NPIPE*STG_B) // 98304

__device__ __forceinline__ void gemm_bf16_tile(const __nv_bfloat16* __restrict__ Ahi_g,
                                               const __nv_bfloat16* __restrict__ Alo_g,
                                               const __nv_bfloat16* __restrict__ Bhi_g,
                                               const __nv_bfloat16* __restrict__ Blo_g,
                                               int row0, int col0,
                                               float acc[4][4][4])
{
    extern __shared__ char smc[];
    const int tid  = threadIdx.x;
    const int wid  = tid >> 5, lane = tid & 31;
    const int warpM = wid >> 2, warpN = wid & 3;

    // cp.async: 256 chunks (16B) per plane, 1 per thread per plane
    const int crow = tid >> 1;
    const int cc   = tid & 1;
    const uint32_t smb = smem_u32(smc);
    const uint32_t dof = smb + (uint32_t)(crow * GROW + cc * 16);
    const size_t offA = (size_t)(row0 + crow) * Dm + cc * 8;
    const size_t offB = (size_t)(col0 + crow) * Dm + cc * 8;

    // LDSM lane bases (R13-verified relative mapping)
    const uint32_t aBase = smb +
        (uint32_t)((warpM * 64 + (lane & 15)) * GROW + ((lane >> 4) * 16));
    const uint32_t bBase = smb + 2*PLANE_B +
        (uint32_t)((warpN * 32 + (lane & 7) + ((lane >> 4) << 3)) * GROW +
                   (((lane >> 3) & 1) * 16));

    const int NST = Dm / KTB;          // 64 stages

    // Prologue: issue stages 0..2
    #pragma unroll
    for (int ps = 0; ps < 3; ps++) {
        const uint32_t bo = (uint32_t)ps * STG_B;
        const int ko = ps * KTB;
        CP16(dof + bo,               Ahi_g + offA + ko);
        CP16(dof + bo +   PLANE_B,   Alo_g + offA + ko);
        CP16(dof + bo + 2*PLANE_B,   Bhi_g + offB + ko);
        CP16(dof + bo + 3*PLANE_B,   Blo_g + offB + ko);
        CP_COMMIT();
    }

    for (int s = 0; s < NST; s++) {
        CP_WAIT2();          // stage s arrived (<=2 newer groups pending)
        __syncthreads();     // all warps: stage s visible, stage s-1 compute done

        if (s + 3 < NST) {   // refill buffer (s+3)&3 == (s-1)&3 (safe post-sync)
            const uint32_t bo = (uint32_t)((s + 3) & 3) * STG_B;
            const int ko = (s + 3) * KTB;
            CP16(dof + bo,               Ahi_g + offA + ko);
            CP16(dof + bo +   PLANE_B,   Alo_g + offA + ko);
            CP16(dof + bo + 2*PLANE_B,   Bhi_g + offB + ko);
            CP16(dof + bo + 3*PLANE_B,   Blo_g + offB + ko);
            CP_COMMIT();
        }

        const uint32_t sb = (uint32_t)(s & 3) * STG_B;

        uint32_t ah[4][4], al[4][4], bh[2][4], bl[2][4];
        #pragma unroll
        for (int mi = 0; mi < 4; mi++) {
            LDSM4(ah[mi], aBase + sb + mi*(16*GROW));
            LDSM4(al[mi], aBase + sb + PLANE_B + mi*(16*GROW));
        }
        #pragma unroll
        for (int p = 0; p < 2; p++) {
            LDSM4(bh[p], bBase + sb + p*(16*GROW));
            LDSM4(bl[p], bBase + sb + PLANE_B + p*(16*GROW));
        }
        #pragma unroll
        for (int mi = 0; mi < 4; mi++)
            #pragma unroll
            for (int ni = 0; ni < 4; ni++) {
                const uint32_t b0h = bh[ni>>1][(ni&1)*2],
                               b1h = bh[ni>>1][(ni&1)*2+1];
                const uint32_t b0l = bl[ni>>1][(ni&1)*2],
                               b1l = bl[ni>>1][(ni&1)*2+1];
                mma_bf16_16x8x16(acc[mi][ni], al[mi], b0h, b1h);
                mma_bf16_16x8x16(acc[mi][ni], ah[mi], b0l, b1l);
                mma_bf16_16x8x16(acc[mi][ni], ah[mi], b0h, b1h);
            }
    }
    __syncthreads();
}

// ===========================================================================
// QKV projection; epilogue writes bf16 hi/lo planes.
// Q pre-scaled 1/8; V written TRANSPOSED [B,H,HD,S].
// ===========================================================================
__global__ __launch_bounds__(256, 2)
void qkv_mma(const float* __restrict__ bq, const float* __restrict__ bk,
             const float* __restrict__ bv)
{
    const int z = blockIdx.z;
    const float* bias = (z == 0) ? bq : (z == 1) ? bk : bv;
    const float scale = (z == 0) ? 0.125f : 1.0f;

    float acc[4][4][4];
    #pragma unroll
    for (int mi = 0; mi < 4; mi++)
        #pragma unroll
        for (int ni = 0; ni < 4; ni++)
            #pragma unroll
            for (int j = 0; j < 4; j++) acc[mi][ni][j] = 0.f;

    const int row0 = blockIdx.y * 128;
    const int col0 = blockIdx.x * 128;
    gemm_bf16_tile(g_xhi, g_xlo, g_whi[z], g_wlo[z], row0, col0, acc);

    const int tid  = threadIdx.x;
    const int wid  = tid >> 5, lane = tid & 31;
    const int warpM = wid >> 2, warpN = wid & 3;
    const int quad = lane >> 2, tq = lane & 3;

    #pragma unroll
    for (int mi = 0; mi < 4; mi++) {
        #pragma unroll
        for (int half = 0; half < 2; half++) {
            const int r = row0 + warpM * 64 + mi * 16 + quad + half * 8;
            const int b = r >> 11;
            const int sq = r & 2047;
            #pragma unroll
            for (int ni = 0; ni < 4; ni++) {
                const int c  = col0 + warpN * 32 + ni * 8 + 2 * tq;
                const int h  = c >> 6;
                const int hd = c & 63;
                float2 bb = *(const float2*)&bias[c];
                float vx = (acc[mi][ni][half*2+0] + bb.x) * scale;
                float vy = (acc[mi][ni][half*2+1] + bb.y) * scale;
                uint32_t hp, lp;
                splitb(vx, vy, hp, lp);
                if (z == 2) {
                    const size_t ot = ((size_t)(b * Hn + h) * Hd + hd) * Seq + sq;
                    __nv_bfloat162 h2 = *(__nv_bfloat162*)&hp;
                    __nv_bfloat162 l2 = *(__nv_bfloat162*)&lp;
                    g_vthi[ot]       = h2.x;  g_vthi[ot + Seq] = h2.y;
                    g_vtlo[ot]       = l2.x;  g_vtlo[ot + Seq] = l2.y;
                } else {
                    const size_t o = (((size_t)(b * Hn + h) * Seq + sq) * Hd + hd);
                    if (z == 0) {
                        *(uint32_t*)&g_qhi[o] = hp;
                        *(uint32_t*)&g_qlo[o] = lp;
                    } else {
                        *(uint32_t*)&g_khi[o] = hp;
                        *(uint32_t*)&g_klo[o] = lp;
                    }
                }
            }
        }
    }
}

// ===========================================================================
// Output projection: out = att @ Wo^T + bo + comp
// ===========================================================================
__global__ __launch_bounds__(256, 2)
void proj_mma(const float* __restrict__ bo, const float* __restrict__ comp,
              float* __restrict__ out)
{
    float acc[4][4][4];
    #pragma unroll
    for (int mi = 0; mi < 4; mi++)
        #pragma unroll
        for (int ni = 0; ni < 4; ni++)
            #pragma unroll
            for (int j = 0; j < 4; j++) acc[mi][ni][j] = 0.f;

    const int row0 = blockIdx.y * 128;
    const int col0 = blockIdx.x * 128;
    gemm_bf16_tile(g_ahi, g_alo, g_whi[3], g_wlo[3], row0, col0, acc);

    const int tid  = threadIdx.x;
    const int wid  = tid >> 5, lane = tid & 31;
    const int warpM = wid >> 2, warpN = wid & 3;
    const int quad = lane >> 2, tq = lane & 3;

    #pragma unroll
    for (int mi = 0; mi < 4; mi++) {
        #pragma unroll
        for (int half = 0; half < 2; half++) {
            const int r = row0 + warpM * 64 + mi * 16 + quad + half * 8;
            #pragma unroll
            for (int ni = 0; ni < 4; ni++) {
                const int c = col0 + warpN * 32 + ni * 8 + 2 * tq;
                float2 bb = *(const float2*)&bo[c];
                float2 cc = *(const float2*)&comp[c];
                float2 v;
                v.x = acc[mi][ni][half * 2 + 0] + bb.x + cc.x;
                v.y = acc[mi][ni][half * 2 + 1] + bb.y + cc.y;
                *(float2*)(out + (size_t)r * Dm + c) = v;
            }
        }
    }
}

// ===========================================================================
// Flash attention, 3xBF16 + LDSM. BM=128, BN=64, 256 threads (8 warps).
// P packed directly from S C-fragments. qt launched DESCENDING (LPT).
// ===========================================================================
#define FPAD 72
#define FROW 144
#define QP_B   (128*FROW)           // 18432: Q staging only
#define KPLANE (64*FROW)            // 9216
#define FSTGB  (4*KPLANE)           // 36864: Khi|Klo|VThi|VTlo
#define FLASH_SMEM_BYTES (QP_B + 2*FSTGB)   // 92160

__global__ __launch_bounds__(256, 2)
void flash_mma()
{
    const int qt = (int)gridDim.x - 1 - (int)blockIdx.x;   // descending: long CTAs first
    const int bh = blockIdx.y;           // 0..63
    const size_t bho = (size_t)bh * Seq * Hd;    // K/Q base
    const size_t bhv = (size_t)bh * Hd * Seq;    // VT base

    extern __shared__ char fsm[];
    const uint32_t qpb = smem_u32(fsm);          // Q staging
    const uint32_t st0 = qpb + QP_B;             // KV stage 0

    const int tid  = threadIdx.x;
    const int wid  = tid >> 5, lane = tid & 31;
    const int quad = lane >> 2, tq = lane & 3;
    const int r0   = wid * 16;

    // cp.async slots: 512 chunks per plane, 2/thread
    uint32_t koff[2];
    size_t ksrc[2], vsrc[2];
    #pragma unroll
    for (int i = 0; i < 2; i++) {
        int id = i * 256 + tid;
        int row = id >> 3, c = id & 7;
        koff[i] = (uint32_t)(row * FROW + c * 16);
        ksrc[i] = (size_t)row * Hd + c * 8;
        vsrc[i] = (size_t)row * Seq + c * 8;
    }

    // LDSM lane bases
    const uint32_t qBase = qpb +
        (uint32_t)((r0 + (lane & 15)) * FROW + (lane >> 4) * 16);
    const uint32_t kBase = st0 +
        (uint32_t)(((lane & 7) + ((lane >> 4) << 3)) * FROW +
                   (((lane >> 3) & 1) * 16));

    // ---- Prologue: Qhi + stage 0, then Qlo ----
    #pragma unroll
    for (int i = 0; i < 4; i++) {
        int id = i * 256 + tid;
        int row = id >> 3, c = id & 7;
        CP16(qpb + (uint32_t)(row * FROW + c * 16),
             g_qhi + bho + (size_t)(qt * 128 + row) * Hd + c * 8);
    }
    #pragma unroll
    for (int i = 0; i < 2; i++) {
        CP16(st0 + koff[i],              g_khi  + bho + ksrc[i]);
        CP16(st0 + KPLANE + koff[i],     g_klo  + bho + ksrc[i]);
        CP16(st0 + 2*KPLANE + koff[i],   g_vthi + bhv + vsrc[i]);
        CP16(st0 + 3*KPLANE + koff[i],   g_vtlo + bhv + vsrc[i]);
    }
    CP_COMMIT();
    CP_WAIT0();
    __syncthreads();

    uint32_t qhi[4][4], qlo[4][4];
    #pragma unroll
    for (int kk = 0; kk < 4; kk++) LDSM4(qhi[kk], qBase + kk * 32);
    __syncthreads();
    #pragma unroll
    for (int i = 0; i < 4; i++) {
        int id = i * 256 + tid;
        int row = id >> 3, c = id & 7;
        CP16(qpb + (uint32_t)(row * FROW + c * 16),
             g_qlo + bho + (size_t)(qt * 128 + row) * Hd + c * 8);
    }
    CP_COMMIT();
    CP_WAIT0();
    __syncthreads();
    #pragma unroll
    for (int kk = 0; kk < 4; kk++) LDSM4(qlo[kk], qBase + kk * 32);

    float m_i[2] = { -1e30f, -1e30f };
    float l_i[2] = { 0.f, 0.f };
    float oacc[8][4];
    #pragma unroll
    for (int ni = 0; ni < 8; ni++)
        #pragma unroll
        for (int j = 0; j < 4; j++) oacc[ni][j] = 0.f;

    const int jend = 2 * qt + 1;
    const int ig0  = qt * 128 + r0 + quad;

    for (int jt = 0; jt <= jend; jt++) {
        __syncthreads();

        const int cur = jt & 1;
        if (jt + 1 <= jend) {
            const uint32_t sb = st0 + (uint32_t)((jt + 1) & 1) * FSTGB;
            const size_t kro = (size_t)((jt + 1) * 64) * Hd;
            const size_t vro = (size_t)((jt + 1) * 64);
            #pragma unroll
            for (int i = 0; i < 2; i++) {
                CP16(sb + koff[i],              g_khi  + bho + kro + ksrc[i]);
                CP16(sb + KPLANE + koff[i],     g_klo  + bho + kro + ksrc[i]);
                CP16(sb + 2*KPLANE + koff[i],   g_vthi + bhv + vro + vsrc[i]);
                CP16(sb + 3*KPLANE + koff[i],   g_vtlo + bhv + vro + vsrc[i]);
            }
            CP_COMMIT();
            CP_WAIT1();
        } else {
            CP_WAIT0();
        }
        __syncthreads();

        // Causal skip: at the last KV tile, rows 0-63 (warps 0-3) are fully
        // masked -> contribute exactly zero; skip their compute entirely.
        if (jt == jend && wid < 4) continue;

        const uint32_t kB = kBase + (uint32_t)cur * FSTGB;
        const uint32_t vB = kB + 2 * KPLANE;

        // ---- S = Q K^T (3xBF16, LDSM B-frags) ----
        float sacc[8][4];
        #pragma unroll
        for (int ni = 0; ni < 8; ni++)
            #pragma unroll
            for (int j = 0; j < 4; j++) sacc[ni][j] = 0.f;

        #pragma unroll
        for (int p = 0; p < 4; p++) {
            #pragma unroll
            for (int kk = 0; kk < 4; kk++) {
                uint32_t kh[4], kl[4];
                LDSM4(kh, kB + p * (16 * FROW) + kk * 32);
                LDSM4(kl, kB + KPLANE + p * (16 * FROW) + kk * 32);
                mma_bf16_16x8x16(sacc[2*p],   qlo[kk], kh[0], kh[1]);
                mma_bf16_16x8x16(sacc[2*p],   qhi[kk], kl[0], kl[1]);
                mma_bf16_16x8x16(sacc[2*p],   qhi[kk], kh[0], kh[1]);
                mma_bf16_16x8x16(sacc[2*p+1], qlo[kk], kh[2], kh[3]);
                mma_bf16_16x8x16(sacc[2*p+1], qhi[kk], kl[2], kl[3]);
                mma_bf16_16x8x16(sacc[2*p+1], qhi[kk], kh[2], kh[3]);
            }
        }

        // ---- causal mask ----
        if (jt >= 2 * qt) {
            const int jg0 = jt * 64;
            #pragma unroll
            for (int ni = 0; ni < 8; ni++) {
                const int jg = jg0 + ni * 8 + 2 * tq;
                if (jg     > ig0)      sacc[ni][0] = -1e30f;
                if (jg + 1 > ig0)      sacc[ni][1] = -1e30f;
                if (jg     > ig0 + 8)  sacc[ni][2] = -1e30f;
                if (jg + 1 > ig0 + 8)  sacc[ni][3] = -1e30f;
            }
        }

        // ---- online softmax ----
        float mloc0 = -1e30f, mloc1 = -1e30f;
        #pragma unroll
        for (int ni = 0; ni < 8; ni++) {
            mloc0 = fmaxf(mloc0, fmaxf(sacc[ni][0], sacc[ni][1]));
            mloc1 = fmaxf(mloc1, fmaxf(sacc[ni][2], sacc[ni][3]));
        }
        #pragma unroll
        for (int off = 1; off < 4; off <<= 1) {
            mloc0 = fmaxf(mloc0, __shfl_xor_sync(0xffffffffu, mloc0, off));
            mloc1 = fmaxf(mloc1, __shfl_xor_sync(0xffffffffu, mloc1, off));
        }
        const float mnew0 = fmaxf(m_i[0], mloc0);
        const float mnew1 = fmaxf(m_i[1], mloc1);
        const float al0 = __expf(m_i[0] - mnew0);
        const float al1 = __expf(m_i[1] - mnew1);
        float ps0 = 0.f, ps1 = 0.f;
        #pragma unroll
        for (int ni = 0; ni < 8; ni++) {
            sacc[ni][0] = __expf(sacc[ni][0] - mnew0);
            sacc[ni][1] = __expf(sacc[ni][1] - mnew0);
            sacc[ni][2] = __expf(sacc[ni][2] - mnew1);
            sacc[ni][3] = __expf(sacc[ni][3] - mnew1);
            ps0 += sacc[ni][0] + sacc[ni][1];
            ps1 += sacc[ni][2] + sacc[ni][3];
        }
        #pragma unroll
        for (int off = 1; off < 4; off <<= 1) {
            ps0 += __shfl_xor_sync(0xffffffffu, ps0, off);
            ps1 += __shfl_xor_sync(0xffffffffu, ps1, off);
        }
        l_i[0] = l_i[0] * al0 + ps0;  m_i[0] = mnew0;
        l_i[1] = l_i[1] * al1 + ps1;  m_i[1] = mnew1;
        #pragma unroll
        for (int ni = 0; ni < 8; ni++) {
            oacc[ni][0] *= al0; oacc[ni][1] *= al0;
            oacc[ni][2] *= al1; oacc[ni][3] *= al1;
        }

        // ---- O += P V: P packed DIRECTLY from S C-fragments ----
        #pragma unroll
        for (int kk = 0; kk < 4; kk++) {
            uint32_t ph[4], pl[4];
            splitb(sacc[2*kk][0],   sacc[2*kk][1],   ph[0], pl[0]);
            splitb(sacc[2*kk][2],   sacc[2*kk][3],   ph[1], pl[1]);
            splitb(sacc[2*kk+1][0], sacc[2*kk+1][1], ph[2], pl[2]);
            splitb(sacc[2*kk+1][2], sacc[2*kk+1][3], ph[3], pl[3]);
            #pragma unroll
            for (int p = 0; p < 4; p++) {
                uint32_t vh[4], vl[4];
                LDSM4(vh, vB + p * (16 * FROW) + kk * 32);
                LDSM4(vl, vB + KPLANE + p * (16 * FROW) + kk * 32);
                mma_bf16_16x8x16(oacc[2*p],   pl, vh[0], vh[1]);
                mma_bf16_16x8x16(oacc[2*p],   ph, vl[0], vl[1]);
                mma_bf16_16x8x16(oacc[2*p],   ph, vh[0], vh[1]);
                mma_bf16_16x8x16(oacc[2*p+1], pl, vh[2], vh[3]);
                mma_bf16_16x8x16(oacc[2*p+1], ph, vl[2], vl[3]);
                mma_bf16_16x8x16(oacc[2*p+1], ph, vh[2], vh[3]);
            }
        }
    }

    // ---- normalize + write bf16 hi/lo att to [B,S,H,HD] ----
    const int bidx = bh >> 4, h = bh & 15;
    #pragma unroll
    for (int half = 0; half < 2; half++) {
        const float inv = 1.0f / l_i[half];
        const int s = qt * 128 + r0 + quad + half * 8;
        const size_t dof = ((size_t)bidx * Seq + s) * Hn * Hd + (size_t)h * Hd;
        #pragma unroll
        for (int ni = 0; ni < 8; ni++) {
            float vx = oacc[ni][half * 2 + 0] * inv;
            float vy = oacc[ni][half * 2 + 1] * inv;
            uint32_t hp, lp;
            splitb(vx, vy, hp, lp);
            *(uint32_t*)&g_ahi[dof + ni * 8 + 2 * tq] = hp;
            *(uint32_t*)&g_alo[dof + ni * 8 + 2 * tq] = lp;
        }
    }
}

// ---------------------------------------------------------------------------
extern "C" void kernel_launch(void* const* d_in, const int* in_sizes, int n_in,
                              void* d_out, int out_size)
{
    (void)in_sizes; (void)n_in; (void)out_size;
    const float* X    = (const float*)d_in[0];
    const float* Wq   = (const float*)d_in[1];
    const float* bq   = (const float*)d_in[2];
    const float* Wk   = (const float*)d_in[3];
    const float* bk   = (const float*)d_in[4];
    const float* Wv   = (const float*)d_in[5];
    const float* bv   = (const float*)d_in[6];
    const float* Wo   = (const float*)d_in[7];
    const float* bo   = (const float*)d_in[8];
    const float* comp = (const float*)d_in[9];
    float* out = (float*)d_out;

    cudaFuncSetAttribute(qkv_mma,   cudaFuncAttributeMaxDynamicSharedMemorySize, GEMM_SMEM_BYTES);
    cudaFuncSetAttribute(proj_mma,  cudaFuncAttributeMaxDynamicSharedMemorySize, GEMM_SMEM_BYTES);
    cudaFuncSetAttribute(flash_mma, cudaFuncAttributeMaxDynamicSharedMemorySize, FLASH_SMEM_BYTES);

    dim3 gS(512, 5);                     // split X + 4 W's
    split_xw<<<gS, 256>>>(X, Wq, Wk, Wv, Wo);

    dim3 gQKV(Dm/128, Mrows/128, 3);     // (8, 64, 3)
    qkv_mma<<<gQKV, 256, GEMM_SMEM_BYTES>>>(bq, bk, bv);

    dim3 gFA(Seq/128, Bsz*Hn);           // (16, 64)
    flash_mma<<<gFA, 256, FLASH_SMEM_BYTES>>>();

    dim3 gP(Dm/128, Mrows/128);          // (8, 64)
    proj_mma<<<gP, 256, GEMM_SMEM_BYTES>>>(bo, comp, out);
}